// round 1
// baseline (speedup 1.0000x reference)
#include <cuda_runtime.h>
#include <cuda_bf16.h>
#include <cstdint>

// Problem-fixed dimensions
#define C_LVL   256
#define H0      200
#define W0      304
#define H1      100
#define W1      152
#define H2      50
#define W2      76
#define HW0     (H0 * W0)          // 60800
#define C_TOT   768
#define OUT_HW  49                 // 7x7

// Scratch: upsampled level-1 and level-2 feature maps at 200x304
__device__ float g_up1[C_LVL * HW0];
__device__ float g_up2[C_LVL * HW0];

// ---------------------------------------------------------------------------
// Bilinear upsample (half-pixel centers, edge clamp) == jax.image.resize
// coord = (j + 0.5)/R - 0.5, clamped to [0, in-1]
// ---------------------------------------------------------------------------
template <int R, int Hi, int Wi, int LEVEL>
__global__ void upsample_kernel(const float* __restrict__ in) {
    const int Ho = Hi * R, Wo = Wi * R;
    int idx = blockIdx.x * blockDim.x + threadIdx.x;
    if (idx >= C_LVL * Ho * Wo) return;

    int x = idx % Wo;
    int t = idx / Wo;
    int y = t % Ho;
    int c = t / Ho;

    float fy = (y + 0.5f) * (1.0f / R) - 0.5f;
    float fx = (x + 0.5f) * (1.0f / R) - 0.5f;
    fy = fminf(fmaxf(fy, 0.0f), (float)(Hi - 1));
    fx = fminf(fmaxf(fx, 0.0f), (float)(Wi - 1));
    int y0 = (int)fy;
    int x0 = (int)fx;
    int y1 = min(y0 + 1, Hi - 1);
    int x1 = min(x0 + 1, Wi - 1);
    float ly = fy - (float)y0;
    float lx = fx - (float)x0;
    float hy = 1.0f - ly, hx = 1.0f - lx;

    const float* p = in + (size_t)c * (Hi * Wi);
    float v = hy * (hx * __ldg(p + y0 * Wi + x0) + lx * __ldg(p + y0 * Wi + x1))
            + ly * (hx * __ldg(p + y1 * Wi + x0) + lx * __ldg(p + y1 * Wi + x1));

    if (LEVEL == 1) g_up1[idx] = v;
    else            g_up2[idx] = v;
}

// ---------------------------------------------------------------------------
// RoIAlign over the (virtual) fused [768, 200, 304] map.
// Block: one (roi, 16-channel group). 196 threads = 4 lanes x 49 outputs.
// Each thread computes its 2x2 sub-sample taps once, then loops 4 channels.
// Grid x is roi-fastest so the concurrent wave shares channel planes in L2.
// ---------------------------------------------------------------------------
#define CH_PER_BLOCK 16
#define NLANES 4
#define ROI_THREADS (NLANES * OUT_HW)   // 196

__global__ __launch_bounds__(ROI_THREADS) void roi_align_kernel(
    const float* __restrict__ feat0,
    const float* __restrict__ boxes,
    const int*   __restrict__ img_h,
    const int*   __restrict__ img_w,
    float* __restrict__ out,
    int N)
{
    int bx  = blockIdx.x;
    int roi = bx % N;
    int grp = bx / N;
    int tid = threadIdx.x;
    int lane = tid / OUT_HW;        // 0..3
    int o    = tid - lane * OUT_HW; // 0..48
    int oh = o / 7, ow = o - oh * 7;

    int c_base = grp * CH_PER_BLOCK;
    const float* base;
    if (c_base < C_LVL)            base = feat0 + (size_t)c_base * HW0;
    else if (c_base < 2 * C_LVL)   base = g_up1 + (size_t)(c_base - C_LVL) * HW0;
    else                           base = g_up2 + (size_t)(c_base - 2 * C_LVL) * HW0;

    float sx = (float)W0 / (float)__ldg(img_w);
    float sy = (float)H0 / (float)__ldg(img_h);

    float bx1 = __ldg(boxes + roi * 4 + 0) * sx;
    float by1 = __ldg(boxes + roi * 4 + 1) * sy;
    float bx2 = __ldg(boxes + roi * 4 + 2) * sx;
    float by2 = __ldg(boxes + roi * 4 + 3) * sy;
    float rw = fmaxf(bx2 - bx1, 1.0f);
    float rh = fmaxf(by2 - by1, 1.0f);
    float bw = rw * (1.0f / 7.0f);
    float bh = rh * (1.0f / 7.0f);

    int   ry[2][2];     // row byte offsets (y0*W, y1*W) per sub-sample
    int   cx[2][2];     // col indices
    float wy[2][2], wx[2][2];
    bool  vy[2], vx[2];

#pragma unroll
    for (int k = 0; k < 2; k++) {
        float offs = (k + 0.5f) * 0.5f;   // (k+0.5)/ratio, ratio=2

        float Y = by1 + ((float)oh + offs) * bh;
        vy[k] = (Y >= -1.0f) && (Y <= (float)H0);
        float Yc = fminf(fmaxf(Y, 0.0f), (float)(H0 - 1));
        int y0 = (int)Yc;
        int y1 = min(y0 + 1, H0 - 1);
        float ly = Yc - (float)y0;
        ry[k][0] = y0 * W0; ry[k][1] = y1 * W0;
        wy[k][0] = 1.0f - ly; wy[k][1] = ly;

        float X = bx1 + ((float)ow + offs) * bw;
        vx[k] = (X >= -1.0f) && (X <= (float)W0);
        float Xc = fminf(fmaxf(X, 0.0f), (float)(W0 - 1));
        int x0 = (int)Xc;
        int x1 = min(x0 + 1, W0 - 1);
        float lx = Xc - (float)x0;
        cx[k][0] = x0; cx[k][1] = x1;
        wx[k][0] = 1.0f - lx; wx[k][1] = lx;
    }

    float* op = out + ((size_t)roi * C_TOT + c_base) * OUT_HW + o;

    for (int cc = lane; cc < CH_PER_BLOCK; cc += NLANES) {
        const float* p = base + (size_t)cc * HW0;
        float acc = 0.0f;
#pragma unroll
        for (int ky = 0; ky < 2; ky++) {
#pragma unroll
            for (int kx = 0; kx < 2; kx++) {
                if (vy[ky] && vx[kx]) {
                    float v00 = __ldg(p + ry[ky][0] + cx[kx][0]);
                    float v01 = __ldg(p + ry[ky][0] + cx[kx][1]);
                    float v10 = __ldg(p + ry[ky][1] + cx[kx][0]);
                    float v11 = __ldg(p + ry[ky][1] + cx[kx][1]);
                    acc += wy[ky][0] * (wx[kx][0] * v00 + wx[kx][1] * v01)
                         + wy[ky][1] * (wx[kx][0] * v10 + wx[kx][1] * v11);
                }
            }
        }
        op[(size_t)cc * OUT_HW] = acc * 0.25f;
    }
}

// ---------------------------------------------------------------------------
// Launch
// ---------------------------------------------------------------------------
extern "C" void kernel_launch(void* const* d_in, const int* in_sizes, int n_in,
                              void* d_out, int out_size) {
    const float* feat0 = (const float*)d_in[0];
    const float* feat1 = (const float*)d_in[1];
    const float* feat2 = (const float*)d_in[2];
    const float* boxes = (const float*)d_in[3];
    const int*   img_h = (const int*)d_in[4];
    const int*   img_w = (const int*)d_in[5];
    float* out = (float*)d_out;

    int N = in_sizes[3] / 4;

    // Upsample level 1 (2x) and level 2 (4x) to 200x304
    {
        int total = C_LVL * HW0;
        int threads = 256;
        int blocks = (total + threads - 1) / threads;
        upsample_kernel<2, H1, W1, 1><<<blocks, threads>>>(feat1);
        upsample_kernel<4, H2, W2, 2><<<blocks, threads>>>(feat2);
    }

    // RoIAlign
    {
        int n_groups = C_TOT / CH_PER_BLOCK;   // 48
        dim3 grid(N * n_groups);
        roi_align_kernel<<<grid, ROI_THREADS>>>(feat0, boxes, img_h, img_w, out, N);
    }
}

// round 2
// speedup vs baseline: 1.0611x; 1.0611x over previous
#include <cuda_runtime.h>
#include <cuda_bf16.h>
#include <cstdint>

// Problem-fixed dimensions
#define C_LVL   256
#define H0      200
#define W0      304
#define H1      100
#define W1      152
#define H2      50
#define W2      76
#define HW0     (H0 * W0)          // 60800
#define C_TOT   768
#define OUT_HW  49                 // 7x7

// Fused multi-scale feature map in HWC layout: [H0, W0, 768]
__device__ float g_fused[(size_t)HW0 * C_TOT];

// ---------------------------------------------------------------------------
// Prep: build g_fused (HWC).
//  cb 0..7  : transpose feat0 channels 0..255
//  cb 8..15 : 2x bilinear upsample of feat1 -> channels 256..511
//  cb 16..23: 4x bilinear upsample of feat2 -> channels 512..767
// Block = 256 threads, handles 32 channels x 32 pixels of one row.
// smem tile transpose gives coalesced reads (CHW) and coalesced writes (HWC).
// ---------------------------------------------------------------------------
__global__ __launch_bounds__(256) void prep_kernel(
    const float* __restrict__ f0,
    const float* __restrict__ f1,
    const float* __restrict__ f2)
{
    int y    = blockIdx.y;          // 0..199
    int xblk = blockIdx.x * 32;     // pixel run start
    int cb   = blockIdx.z;          // 0..23
    int warp = threadIdx.x >> 5;
    int lane = threadIdx.x & 31;
    int x    = xblk + lane;

    __shared__ float tile[32][33];  // [c_local][px]

    if (cb < 8) {
        // --- level 0: straight transpose ---
        int c0 = cb * 32;
        if (x < W0) {
            const float* src = f0 + (size_t)c0 * HW0 + y * W0 + x;
#pragma unroll
            for (int p = 0; p < 4; p++) {
                int cl = p * 8 + warp;
                tile[cl][lane] = __ldg(src + (size_t)cl * HW0);
            }
        }
    } else if (cb < 16) {
        // --- level 1: 2x upsample ---
        int c0l = cb * 32 - 256;
        float fy = (y + 0.5f) * 0.5f - 0.5f;
        fy = fminf(fmaxf(fy, 0.0f), (float)(H1 - 1));
        int y0 = (int)fy, y1 = min(y0 + 1, H1 - 1);
        float ly = fy - (float)y0, hy = 1.0f - ly;
        if (x < W0) {
            float fx = (x + 0.5f) * 0.5f - 0.5f;
            fx = fminf(fmaxf(fx, 0.0f), (float)(W1 - 1));
            int x0 = (int)fx, x1 = min(x0 + 1, W1 - 1);
            float lx = fx - (float)x0, hx = 1.0f - lx;
#pragma unroll
            for (int p = 0; p < 4; p++) {
                int cl = p * 8 + warp;
                const float* pl = f1 + (size_t)(c0l + cl) * (H1 * W1);
                tile[cl][lane] =
                    hy * (hx * __ldg(pl + y0 * W1 + x0) + lx * __ldg(pl + y0 * W1 + x1))
                  + ly * (hx * __ldg(pl + y1 * W1 + x0) + lx * __ldg(pl + y1 * W1 + x1));
            }
        }
    } else {
        // --- level 2: 4x upsample ---
        int c0l = cb * 32 - 512;
        float fy = (y + 0.5f) * 0.25f - 0.5f;
        fy = fminf(fmaxf(fy, 0.0f), (float)(H2 - 1));
        int y0 = (int)fy, y1 = min(y0 + 1, H2 - 1);
        float ly = fy - (float)y0, hy = 1.0f - ly;
        if (x < W0) {
            float fx = (x + 0.5f) * 0.25f - 0.5f;
            fx = fminf(fmaxf(fx, 0.0f), (float)(W2 - 1));
            int x0 = (int)fx, x1 = min(x0 + 1, W2 - 1);
            float lx = fx - (float)x0, hx = 1.0f - lx;
#pragma unroll
            for (int p = 0; p < 4; p++) {
                int cl = p * 8 + warp;
                const float* pl = f2 + (size_t)(c0l + cl) * (H2 * W2);
                tile[cl][lane] =
                    hy * (hx * __ldg(pl + y0 * W2 + x0) + lx * __ldg(pl + y0 * W2 + x1))
                  + ly * (hx * __ldg(pl + y1 * W2 + x0) + lx * __ldg(pl + y1 * W2 + x1));
            }
        }
    }
    __syncthreads();

    // write HWC: warp writes 32 consecutive channels of one pixel (128B)
    int c0 = cb * 32;
#pragma unroll
    for (int p = 0; p < 4; p++) {
        int px = p * 8 + warp;
        int xg = xblk + px;
        if (xg < W0)
            g_fused[(size_t)(y * W0 + xg) * C_TOT + c0 + lane] = tile[lane][px];
    }
}

// ---------------------------------------------------------------------------
// RoIAlign over g_fused (HWC).
// Block = 128 threads (4 warps) = one (roi, 128-channel slab).
// Warp = 32 consecutive channels; every tap load is a coalesced 128B line.
// Sample coordinate tables computed once per block into smem.
// Output staged in smem, then written as one contiguous chunk per warp.
// ---------------------------------------------------------------------------
__global__ __launch_bounds__(128) void roi_align_kernel(
    const float* __restrict__ boxes,
    const int*   __restrict__ img_h,
    const int*   __restrict__ img_w,
    float* __restrict__ out)
{
    int roi  = blockIdx.x;
    int cblk = blockIdx.y;                  // 0..5 (128 channels each)
    int tid  = threadIdx.x;
    int w    = tid >> 5;
    int lane = tid & 31;
    int c    = cblk * 128 + w * 32 + lane;  // global channel

    // sample tables: 14 x-samples, 14 y-samples (2 corners + 2 weights each)
    __shared__ int   sxo[14][2];            // x0*768, x1*768
    __shared__ float swx[14][2];
    __shared__ int   syo[14][2];            // y0*W0*768, y1*W0*768
    __shared__ float swy[14][2];
    __shared__ float s_out[4][OUT_HW][33];  // [warp][o][c_local]

    if (tid < 28) {
        bool isx = tid < 14;
        int  s   = isx ? tid : tid - 14;
        int  bin = s >> 1;
        float offs = 0.25f + 0.5f * (float)(s & 1);

        float scale = isx ? ((float)W0 / (float)__ldg(img_w))
                          : ((float)H0 / (float)__ldg(img_h));
        float p1 = __ldg(boxes + roi * 4 + (isx ? 0 : 1)) * scale;
        float p2 = __ldg(boxes + roi * 4 + (isx ? 2 : 3)) * scale;
        float bs = fmaxf(p2 - p1, 1.0f) * (1.0f / 7.0f);
        float P  = p1 + ((float)bin + offs) * bs;

        int lim = isx ? W0 : H0;
        bool valid = (P >= -1.0f) && (P <= (float)lim);
        float Pc = fminf(fmaxf(P, 0.0f), (float)(lim - 1));
        int p0 = (int)Pc;
        int p1i = min(p0 + 1, lim - 1);
        float l = Pc - (float)p0;
        float w0 = valid ? (1.0f - l) : 0.0f;
        float w1 = valid ? l : 0.0f;

        if (isx) {
            sxo[s][0] = p0 * C_TOT;  sxo[s][1] = p1i * C_TOT;
            swx[s][0] = w0;          swx[s][1] = w1;
        } else {
            syo[s][0] = p0 * (W0 * C_TOT);  syo[s][1] = p1i * (W0 * C_TOT);
            swy[s][0] = w0;                 swy[s][1] = w1;
        }
    }
    __syncthreads();

    const float* fc = g_fused + c;

#pragma unroll
    for (int oh = 0; oh < 7; oh++) {
        int   ya0 = syo[2 * oh][0],     ya1 = syo[2 * oh][1];
        int   yb0 = syo[2 * oh + 1][0], yb1 = syo[2 * oh + 1][1];
        float wa0 = swy[2 * oh][0],     wa1 = swy[2 * oh][1];
        float wb0 = swy[2 * oh + 1][0], wb1 = swy[2 * oh + 1][1];
#pragma unroll
        for (int ow = 0; ow < 7; ow++) {
            float acc = 0.0f;
#pragma unroll
            for (int sx = 0; sx < 2; sx++) {
                int   s   = 2 * ow + sx;
                int   x0  = sxo[s][0], x1 = sxo[s][1];
                float u0  = swx[s][0], u1 = swx[s][1];
                // y-sample A
                acc += wa0 * (u0 * __ldg(fc + ya0 + x0) + u1 * __ldg(fc + ya0 + x1))
                     + wa1 * (u0 * __ldg(fc + ya1 + x0) + u1 * __ldg(fc + ya1 + x1));
                // y-sample B
                acc += wb0 * (u0 * __ldg(fc + yb0 + x0) + u1 * __ldg(fc + yb0 + x1))
                     + wb1 * (u0 * __ldg(fc + yb1 + x0) + u1 * __ldg(fc + yb1 + x1));
            }
            s_out[w][oh * 7 + ow][lane] = acc * 0.25f;
        }
    }

    // coalesced store: warp's 32ch x 49 outputs form one contiguous chunk
    float* base = out + ((size_t)roi * C_TOT + cblk * 128 + w * 32) * OUT_HW;
    int o  = lane;      // j % 49 (lane < 32 < 49)
    int cl = 0;         // j / 49
    for (int j = lane; j < 32 * OUT_HW; j += 32) {
        base[j] = s_out[w][o][cl];
        o += 32;
        if (o >= OUT_HW) { o -= OUT_HW; cl++; }
    }
}

// ---------------------------------------------------------------------------
// Launch
// ---------------------------------------------------------------------------
extern "C" void kernel_launch(void* const* d_in, const int* in_sizes, int n_in,
                              void* d_out, int out_size) {
    const float* feat0 = (const float*)d_in[0];
    const float* feat1 = (const float*)d_in[1];
    const float* feat2 = (const float*)d_in[2];
    const float* boxes = (const float*)d_in[3];
    const int*   img_h = (const int*)d_in[4];
    const int*   img_w = (const int*)d_in[5];
    float* out = (float*)d_out;

    int N = in_sizes[3] / 4;

    // Build fused HWC map
    {
        dim3 grid((W0 + 31) / 32, H0, 24);
        prep_kernel<<<grid, 256>>>(feat0, feat1, feat2);
    }

    // RoIAlign
    {
        dim3 grid(N, C_TOT / 128);
        roi_align_kernel<<<grid, 128>>>(boxes, img_h, img_w, out);
    }
}

// round 3
// speedup vs baseline: 1.7303x; 1.6307x over previous
#include <cuda_runtime.h>
#include <cuda_fp16.h>
#include <cstdint>

// Problem-fixed dimensions
#define C_LVL   256
#define H0      200
#define W0      304
#define H1      100
#define W1      152
#define H2      50
#define W2      76
#define HW0     (H0 * W0)          // 60800
#define C_TOT   768
#define OUT_HW  49                 // 7x7

// Fused multi-scale feature map in HWC layout, fp16: [H0*W0, 768]
__device__ __half g_fused[(size_t)HW0 * C_TOT];

// ---------------------------------------------------------------------------
// Prep: build g_fused (HWC, fp16).
//  group 0..3  : transpose feat0 channels (64 each)
//  group 4..7  : 2x bilinear upsample of feat1 -> channels 256..511
//  group 8..11 : 4x bilinear upsample of feat2 -> channels 512..767
// Block = 256 threads: 64 channels x 32 pixels of one row.
// smem transpose: coalesced CHW reads -> coalesced HWC half2 writes.
// ---------------------------------------------------------------------------
__global__ __launch_bounds__(256) void prep_kernel(
    const float* __restrict__ f0,
    const float* __restrict__ f1,
    const float* __restrict__ f2)
{
    int y    = blockIdx.y;          // 0..199
    int xblk = blockIdx.x * 32;     // pixel run start
    int g    = blockIdx.z;          // 0..11 (64-channel groups)
    int warp = threadIdx.x >> 5;
    int lane = threadIdx.x & 31;
    int x    = xblk + lane;

    __shared__ float tile[64][33];  // [c_local][px]

    if (g < 4) {
        // --- level 0: straight transpose ---
        int c0 = g * 64;
        if (x < W0) {
            const float* src = f0 + (size_t)c0 * HW0 + y * W0 + x;
#pragma unroll
            for (int p = 0; p < 8; p++) {
                int cl = warp * 8 + p;
                tile[cl][lane] = __ldg(src + (size_t)cl * HW0);
            }
        }
    } else if (g < 8) {
        // --- level 1: 2x upsample ---
        int c0l = (g - 4) * 64;
        float fy = (y + 0.5f) * 0.5f - 0.5f;
        fy = fminf(fmaxf(fy, 0.0f), (float)(H1 - 1));
        int y0 = (int)fy, y1 = min(y0 + 1, H1 - 1);
        float ly = fy - (float)y0, hy = 1.0f - ly;
        if (x < W0) {
            float fx = (x + 0.5f) * 0.5f - 0.5f;
            fx = fminf(fmaxf(fx, 0.0f), (float)(W1 - 1));
            int x0 = (int)fx, x1 = min(x0 + 1, W1 - 1);
            float lx = fx - (float)x0, hx = 1.0f - lx;
#pragma unroll
            for (int p = 0; p < 8; p++) {
                int cl = warp * 8 + p;
                const float* pl = f1 + (size_t)(c0l + cl) * (H1 * W1);
                tile[cl][lane] =
                    hy * (hx * __ldg(pl + y0 * W1 + x0) + lx * __ldg(pl + y0 * W1 + x1))
                  + ly * (hx * __ldg(pl + y1 * W1 + x0) + lx * __ldg(pl + y1 * W1 + x1));
            }
        }
    } else {
        // --- level 2: 4x upsample ---
        int c0l = (g - 8) * 64;
        float fy = (y + 0.5f) * 0.25f - 0.5f;
        fy = fminf(fmaxf(fy, 0.0f), (float)(H2 - 1));
        int y0 = (int)fy, y1 = min(y0 + 1, H2 - 1);
        float ly = fy - (float)y0, hy = 1.0f - ly;
        if (x < W0) {
            float fx = (x + 0.5f) * 0.25f - 0.5f;
            fx = fminf(fmaxf(fx, 0.0f), (float)(W2 - 1));
            int x0 = (int)fx, x1 = min(x0 + 1, W2 - 1);
            float lx = fx - (float)x0, hx = 1.0f - lx;
#pragma unroll
            for (int p = 0; p < 8; p++) {
                int cl = warp * 8 + p;
                const float* pl = f2 + (size_t)(c0l + cl) * (H2 * W2);
                tile[cl][lane] =
                    hy * (hx * __ldg(pl + y0 * W2 + x0) + lx * __ldg(pl + y0 * W2 + x1))
                  + ly * (hx * __ldg(pl + y1 * W2 + x0) + lx * __ldg(pl + y1 * W2 + x1));
            }
        }
    }
    __syncthreads();

    // write HWC half2: warp writes 64 consecutive channels of one pixel (128B)
    int c0 = g * 64;
#pragma unroll
    for (int q = 0; q < 4; q++) {
        int px = warp * 4 + q;
        int xg = xblk + px;
        if (xg < W0) {
            __half2 v = __floats2half2_rn(tile[2 * lane][px], tile[2 * lane + 1][px]);
            *reinterpret_cast<__half2*>(
                g_fused + (size_t)(y * W0 + xg) * C_TOT + c0 + 2 * lane) = v;
        }
    }
}

// ---------------------------------------------------------------------------
// RoIAlign over g_fused (HWC fp16).
// Block = 128 thr (4 warps) = one (roi, 256-ch slab, output row).
// Lane handles 2 consecutive channels via half2; warp covers 64 ch.
// Grid = N x 3 x 7 (5376 blocks) for occupancy; traffic-neutral split.
// ---------------------------------------------------------------------------
__device__ __forceinline__ float2 ldh2(const __half* p) {
    __half2 h = __ldg(reinterpret_cast<const __half2*>(p));
    return __half22float2(h);
}

__global__ __launch_bounds__(128, 8) void roi_align_kernel(
    const float* __restrict__ boxes,
    const int*   __restrict__ img_h,
    const int*   __restrict__ img_w,
    float* __restrict__ out)
{
    int roi  = blockIdx.x;
    int cblk = blockIdx.y;                  // 0..2 (256 channels each)
    int oh   = blockIdx.z;                  // 0..6
    int tid  = threadIdx.x;
    int w    = tid >> 5;
    int lane = tid & 31;

    __shared__ int   sxo[14][2];            // x0*C, x1*C (half-elem offsets)
    __shared__ float swx[14][2];
    __shared__ int   syo[2][2];             // y0*W0*C, y1*W0*C for this oh
    __shared__ float swy[2][2];
    __shared__ float s_out[256][7];         // [c_local][ow]

    if (tid < 16) {
        bool isx = tid < 14;
        int  s, bin;
        if (isx) { s = tid;      bin = s >> 1; }
        else     { s = tid - 14; bin = oh;     }   // y-sample s=0,1 of this row
        float offs = 0.25f + 0.5f * (float)(isx ? (s & 1) : s);

        float scale = isx ? ((float)W0 / (float)__ldg(img_w))
                          : ((float)H0 / (float)__ldg(img_h));
        float p1 = __ldg(boxes + roi * 4 + (isx ? 0 : 1)) * scale;
        float p2 = __ldg(boxes + roi * 4 + (isx ? 2 : 3)) * scale;
        float bs = fmaxf(p2 - p1, 1.0f) * (1.0f / 7.0f);
        float P  = p1 + ((float)bin + offs) * bs;

        int lim = isx ? W0 : H0;
        bool valid = (P >= -1.0f) && (P <= (float)lim);
        float Pc = fminf(fmaxf(P, 0.0f), (float)(lim - 1));
        int p0  = (int)Pc;
        int p1i = min(p0 + 1, lim - 1);
        float l  = Pc - (float)p0;
        float w0 = valid ? (1.0f - l) : 0.0f;
        float w1 = valid ? l : 0.0f;

        if (isx) {
            sxo[s][0] = p0 * C_TOT;  sxo[s][1] = p1i * C_TOT;
            swx[s][0] = w0;          swx[s][1] = w1;
        } else {
            syo[s][0] = p0 * (W0 * C_TOT);  syo[s][1] = p1i * (W0 * C_TOT);
            swy[s][0] = w0;                 swy[s][1] = w1;
        }
    }
    __syncthreads();

    int c_loc = w * 64 + 2 * lane;
    const __half* fc = g_fused + (size_t)(cblk * 256) + c_loc;

    int   ya0 = syo[0][0], ya1 = syo[0][1];
    int   yb0 = syo[1][0], yb1 = syo[1][1];
    float wa0 = swy[0][0], wa1 = swy[0][1];
    float wb0 = swy[1][0], wb1 = swy[1][1];

#pragma unroll
    for (int ow = 0; ow < 7; ow++) {
        float ax = 0.0f, ay = 0.0f;
#pragma unroll
        for (int sx = 0; sx < 2; sx++) {
            int s = 2 * ow + sx;
            int x0 = sxo[s][0], x1 = sxo[s][1];
            float u0 = swx[s][0], u1 = swx[s][1];
            float2 v; float k;
            k = wa0 * u0; v = ldh2(fc + ya0 + x0); ax += k * v.x; ay += k * v.y;
            k = wa0 * u1; v = ldh2(fc + ya0 + x1); ax += k * v.x; ay += k * v.y;
            k = wa1 * u0; v = ldh2(fc + ya1 + x0); ax += k * v.x; ay += k * v.y;
            k = wa1 * u1; v = ldh2(fc + ya1 + x1); ax += k * v.x; ay += k * v.y;
            k = wb0 * u0; v = ldh2(fc + yb0 + x0); ax += k * v.x; ay += k * v.y;
            k = wb0 * u1; v = ldh2(fc + yb0 + x1); ax += k * v.x; ay += k * v.y;
            k = wb1 * u0; v = ldh2(fc + yb1 + x0); ax += k * v.x; ay += k * v.y;
            k = wb1 * u1; v = ldh2(fc + yb1 + x1); ax += k * v.x; ay += k * v.y;
        }
        s_out[c_loc][ow]     = ax * 0.25f;
        s_out[c_loc + 1][ow] = ay * 0.25f;
    }
    __syncthreads();

    // cooperative semi-coalesced store of the block's [256ch x 7ow] chunk
    float* base = out + ((size_t)roi * C_TOT + cblk * 256) * OUT_HW + oh * 7;
#pragma unroll
    for (int idx = tid; idx < 256 * 7; idx += 128) {
        int c  = idx / 7;
        int owv = idx - 7 * c;
        base[(size_t)c * OUT_HW + owv] = s_out[c][owv];
    }
}

// ---------------------------------------------------------------------------
// Launch
// ---------------------------------------------------------------------------
extern "C" void kernel_launch(void* const* d_in, const int* in_sizes, int n_in,
                              void* d_out, int out_size) {
    const float* feat0 = (const float*)d_in[0];
    const float* feat1 = (const float*)d_in[1];
    const float* feat2 = (const float*)d_in[2];
    const float* boxes = (const float*)d_in[3];
    const int*   img_h = (const int*)d_in[4];
    const int*   img_w = (const int*)d_in[5];
    float* out = (float*)d_out;

    int N = in_sizes[3] / 4;

    // Build fused HWC fp16 map
    {
        dim3 grid((W0 + 31) / 32, H0, 12);
        prep_kernel<<<grid, 256>>>(feat0, feat1, feat2);
    }

    // RoIAlign
    {
        dim3 grid(N, 3, 7);
        roi_align_kernel<<<grid, 128>>>(boxes, img_h, img_w, out);
    }
}

// round 4
// speedup vs baseline: 1.7402x; 1.0057x over previous
#include <cuda_runtime.h>
#include <cuda_fp16.h>
#include <cstdint>

#define H0 200
#define W0 304
#define H1 100
#define W1 152
#define H2 50
#define W2 76
#define HW0 (H0*W0)
#define C_TOT 768

// Fused HWC fp16 map viewed as 8-channel octets (16B) for aligned uint4 access
__device__ uint4 g_fused[(size_t)HW0 * (C_TOT/8)];

// ---------------------------------------------------------------------------
// prep0: transpose feat0 (CHW fp32) -> g_fused channels [0,256) (HWC fp16)
// ---------------------------------------------------------------------------
__global__ __launch_bounds__(256) void prep0_kernel(const float* __restrict__ f0) {
    __shared__ float tile[64][33];
    int y = blockIdx.y, xblk = blockIdx.x * 32, g = blockIdx.z;
    int warp = threadIdx.x >> 5, lane = threadIdx.x & 31;
    int x = xblk + lane;
    int c0 = g * 64;
    if (x < W0) {
        const float* src = f0 + (size_t)c0 * HW0 + y * W0 + x;
#pragma unroll
        for (int p = 0; p < 8; p++) {
            int cl = warp * 8 + p;
            tile[cl][lane] = __ldg(src + (size_t)cl * HW0);
        }
    }
    __syncthreads();
    __half* gf = (__half*)g_fused;
#pragma unroll
    for (int q = 0; q < 4; q++) {
        int px = warp * 4 + q, xg = xblk + px;
        if (xg < W0) {
            __half2 v = __floats2half2_rn(tile[2 * lane][px], tile[2 * lane + 1][px]);
            *(__half2*)(gf + (size_t)(y * W0 + xg) * C_TOT + c0 + 2 * lane) = v;
        }
    }
}

// ---------------------------------------------------------------------------
// prep1: 2x upsample feat1 -> channels [256,512). Constant-phase separable.
// Out rows 2Y,2Y+1 from input rows Y-1,Y,Y+1; out-x pair per lane from 3 inputs.
// ---------------------------------------------------------------------------
#define P1_PAD 65
__global__ __launch_bounds__(256) void prep1_kernel(const float* __restrict__ f1) {
    __shared__ __half tile[2 * 64 * P1_PAD];   // [row][px][ch], pad 65
    int Y  = blockIdx.y;            // out rows 2Y, 2Y+1
    int xb = blockIdx.x * 64;
    int cb = blockIdx.z * 64;
    int warp = threadIdx.x >> 5, lane = threadIdx.x & 31;
    int j  = xb / 2 + lane;
    int xm = max(j - 1, 0), xc = min(j, W1 - 1), xp = min(j + 1, W1 - 1);
    int r0 = max(Y - 1, 0), r1 = Y, r2 = min(Y + 1, H1 - 1);
#pragma unroll
    for (int p = 0; p < 8; p++) {
        int cl = warp * 8 + p;
        const float* pl = f1 + (size_t)(cb + cl) * (H1 * W1);
        float v00 = __ldg(pl + r0 * W1 + xm), v01 = __ldg(pl + r0 * W1 + xc), v02 = __ldg(pl + r0 * W1 + xp);
        float v10 = __ldg(pl + r1 * W1 + xm), v11 = __ldg(pl + r1 * W1 + xc), v12 = __ldg(pl + r1 * W1 + xp);
        float v20 = __ldg(pl + r2 * W1 + xm), v21 = __ldg(pl + r2 * W1 + xc), v22 = __ldg(pl + r2 * W1 + xp);
        float a0 = 0.25f * v00 + 0.75f * v01, b0 = 0.75f * v01 + 0.25f * v02;
        float a1 = 0.25f * v10 + 0.75f * v11, b1 = 0.75f * v11 + 0.25f * v12;
        float a2 = 0.25f * v20 + 0.75f * v21, b2 = 0.75f * v21 + 0.25f * v22;
        float e0 = 0.25f * a0 + 0.75f * a1, o0 = 0.25f * b0 + 0.75f * b1;  // out row 2Y
        float e1 = 0.75f * a1 + 0.25f * a2, o1 = 0.75f * b1 + 0.25f * b2;  // out row 2Y+1
        int px = 2 * lane;
        tile[(0 * 64 + px)     * P1_PAD + cl] = __float2half_rn(e0);
        tile[(0 * 64 + px + 1) * P1_PAD + cl] = __float2half_rn(o0);
        tile[(1 * 64 + px)     * P1_PAD + cl] = __float2half_rn(e1);
        tile[(1 * 64 + px + 1) * P1_PAD + cl] = __float2half_rn(o1);
    }
    __syncthreads();
    __half* gf = (__half*)g_fused;
    for (int i = warp; i < 128; i += 8) {
        int row = i >> 6, px = i & 63;
        int xg = xb + px;
        if (xg < W0) {
            __half lo = tile[(row * 64 + px) * P1_PAD + 2 * lane];
            __half hi = tile[(row * 64 + px) * P1_PAD + 2 * lane + 1];
            *(__half2*)(gf + (size_t)((2 * Y + row) * W0 + xg) * C_TOT + 256 + cb + 2 * lane)
                = __halves2half2(lo, hi);
        }
    }
}

// ---------------------------------------------------------------------------
// prep2: 4x upsample feat2 -> channels [512,768). Out-x quad per lane from 3
// inputs; out-row pair from 2 input rows (phase-constant weights).
// ---------------------------------------------------------------------------
#define P2_PAD 65
__global__ __launch_bounds__(256) void prep2_kernel(const float* __restrict__ f2) {
    __shared__ __half tile[2 * 128 * P2_PAD];   // [row][px][ch]
    int yb = blockIdx.y;            // 0..99
    int Y = yb >> 1, half = yb & 1;
    int xb = blockIdx.x * 128;
    int cb = blockIdx.z * 64;
    int warp = threadIdx.x >> 5, lane = threadIdx.x & 31;
    int j  = xb / 4 + lane;
    int xm = max(j - 1, 0), xc = min(j, W2 - 1), xp = min(j + 1, W2 - 1);
    int ra = half ? Y : max(Y - 1, 0);
    int rb = half ? min(Y + 1, H2 - 1) : Y;
    float wya0, wyb0, wya1, wyb1;
    if (half == 0) { wya0 = 0.375f; wyb0 = 0.625f; wya1 = 0.125f; wyb1 = 0.875f; }
    else           { wya0 = 0.875f; wyb0 = 0.125f; wya1 = 0.625f; wyb1 = 0.375f; }
#pragma unroll
    for (int p = 0; p < 8; p++) {
        int cl = warp * 8 + p;
        const float* pl = f2 + (size_t)(cb + cl) * (H2 * W2);
        float va0 = __ldg(pl + ra * W2 + xm), va1 = __ldg(pl + ra * W2 + xc), va2 = __ldg(pl + ra * W2 + xp);
        float vb0 = __ldg(pl + rb * W2 + xm), vb1 = __ldg(pl + rb * W2 + xc), vb2 = __ldg(pl + rb * W2 + xp);
        float qa[4], qb[4];
        qa[0] = 0.375f * va0 + 0.625f * va1; qa[1] = 0.125f * va0 + 0.875f * va1;
        qa[2] = 0.875f * va1 + 0.125f * va2; qa[3] = 0.625f * va1 + 0.375f * va2;
        qb[0] = 0.375f * vb0 + 0.625f * vb1; qb[1] = 0.125f * vb0 + 0.875f * vb1;
        qb[2] = 0.875f * vb1 + 0.125f * vb2; qb[3] = 0.625f * vb1 + 0.375f * vb2;
        int px = 4 * lane;
#pragma unroll
        for (int q = 0; q < 4; q++) {
            float o0 = wya0 * qa[q] + wyb0 * qb[q];
            float o1 = wya1 * qa[q] + wyb1 * qb[q];
            tile[(0 * 128 + px + q) * P2_PAD + cl] = __float2half_rn(o0);
            tile[(1 * 128 + px + q) * P2_PAD + cl] = __float2half_rn(o1);
        }
    }
    __syncthreads();
    __half* gf = (__half*)g_fused;
    int ybase = 4 * Y + 2 * half;
    for (int i = warp; i < 256; i += 8) {
        int row = i >> 7, px = i & 127;
        int xg = xb + px;
        if (xg < W0) {
            __half lo = tile[(row * 128 + px) * P2_PAD + 2 * lane];
            __half hi = tile[(row * 128 + px) * P2_PAD + 2 * lane + 1];
            *(__half2*)(gf + (size_t)((ybase + row) * W0 + xg) * C_TOT + 512 + cb + 2 * lane)
                = __halves2half2(lo, hi);
        }
    }
}

// ---------------------------------------------------------------------------
// RoIAlign: block = (roi, oh), 96 threads; thread = one 8-channel octet
// (uint4 taps). Merged corner-column tables (duplicates summed) per block.
// ---------------------------------------------------------------------------
__global__ __launch_bounds__(96) void roi_kernel(
    const float* __restrict__ boxes,
    const int*   __restrict__ img_h,
    const int*   __restrict__ img_w,
    float* __restrict__ out)
{
    int roi = blockIdx.x, oh = blockIdx.y;
    int tid = threadIdx.x;

    __shared__ int   s_xo[28];  __shared__ float s_xw[28];
    __shared__ int   s_yo[4];   __shared__ float s_yw[4];
    __shared__ int   s_mxo[7][4]; __shared__ float s_mxw[7][4]; __shared__ int s_mx[7];
    __shared__ int   s_myo[4];    __shared__ float s_myw[4];    __shared__ int s_my;
    __shared__ float s_out[7][776];

    if (tid < 32) {
        bool isx = tid < 28;
        int e = isx ? tid : tid - 28;
        int s = e >> 1, k = e & 1;
        int bin = isx ? (s >> 1) : oh;
        int sub = isx ? (s & 1) : s;
        float offs = 0.25f + 0.5f * (float)sub;
        float scale = isx ? ((float)W0 / (float)__ldg(img_w))
                          : ((float)H0 / (float)__ldg(img_h));
        float p1 = __ldg(boxes + roi * 4 + (isx ? 0 : 1)) * scale;
        float p2 = __ldg(boxes + roi * 4 + (isx ? 2 : 3)) * scale;
        float bs = fmaxf(p2 - p1, 1.0f) * (1.0f / 7.0f);
        float P  = p1 + ((float)bin + offs) * bs;
        int lim = isx ? W0 : H0;
        bool valid = (P >= -1.0f) && (P <= (float)lim);
        float Pc = fminf(fmaxf(P, 0.0f), (float)(lim - 1));
        int c0 = (int)Pc;
        int c1 = min(c0 + 1, lim - 1);
        float l = Pc - (float)c0;
        float wv = valid ? (k ? l : 1.0f - l) : 0.0f;
        int off = (k ? c1 : c0) * (isx ? 96 : W0 * 96);   // octet offsets
        if (isx) { s_xo[e] = off; s_xw[e] = wv; }
        else     { s_yo[e] = off; s_yw[e] = wv; }
    }
    __syncthreads();

    if (tid < 8) {
        if (tid < 7) {          // merge 4 x-entries of bin ow=tid
            int m = 0;
            for (int t = 0; t < 4; t++) {
                float w = s_xw[4 * tid + t];
                if (w == 0.0f) continue;
                int o = s_xo[4 * tid + t];
                int f = -1;
                for (int u = 0; u < m; u++) if (s_mxo[tid][u] == o) { f = u; break; }
                if (f >= 0) s_mxw[tid][f] += w;
                else { s_mxo[tid][m] = o; s_mxw[tid][m] = w; m++; }
            }
            s_mx[tid] = m;
        } else {                // merge the 4 y-entries of this oh
            int m = 0;
            for (int t = 0; t < 4; t++) {
                float w = s_yw[t];
                if (w == 0.0f) continue;
                int o = s_yo[t];
                int f = -1;
                for (int u = 0; u < m; u++) if (s_myo[u] == o) { f = u; break; }
                if (f >= 0) s_myw[f] += w;
                else { s_myo[m] = o; s_myw[m] = w; m++; }
            }
            s_my = m;
        }
    }
    __syncthreads();

    const uint4* base = g_fused + tid;      // this thread's channel octet
    int my = s_my;

#pragma unroll
    for (int ow = 0; ow < 7; ow++) {
        float a0 = 0, a1 = 0, a2 = 0, a3 = 0, a4 = 0, a5 = 0, a6 = 0, a7 = 0;
        int mx = s_mx[ow];
        for (int i = 0; i < my; i++) {
            int   yo = s_myo[i];
            float wy = s_myw[i];
            for (int jj = 0; jj < mx; jj++) {
                float w = wy * s_mxw[ow][jj];
                uint4 v = __ldg(base + yo + s_mxo[ow][jj]);
                const __half2* h = (const __half2*)&v;
                float2 f0 = __half22float2(h[0]);
                float2 f1 = __half22float2(h[1]);
                float2 f2 = __half22float2(h[2]);
                float2 f3 = __half22float2(h[3]);
                a0 += w * f0.x; a1 += w * f0.y;
                a2 += w * f1.x; a3 += w * f1.y;
                a4 += w * f2.x; a5 += w * f2.y;
                a6 += w * f3.x; a7 += w * f3.y;
            }
        }
        float4* d = (float4*)&s_out[ow][tid * 8];
        d[0] = make_float4(a0 * 0.25f, a1 * 0.25f, a2 * 0.25f, a3 * 0.25f);
        d[1] = make_float4(a4 * 0.25f, a5 * 0.25f, a6 * 0.25f, a7 * 0.25f);
    }
    __syncthreads();

    size_t ob = (size_t)roi * C_TOT * 49 + (size_t)oh * 7;
    int c = tid / 7, ow2 = tid % 7;
    for (int i = tid; i < C_TOT * 7; i += 96) {
        out[ob + (size_t)c * 49 + ow2] = s_out[ow2][c];
        ow2 += 5; c += 13;
        if (ow2 >= 7) { ow2 -= 7; c++; }
    }
}

// ---------------------------------------------------------------------------
// Launch
// ---------------------------------------------------------------------------
extern "C" void kernel_launch(void* const* d_in, const int* in_sizes, int n_in,
                              void* d_out, int out_size) {
    const float* feat0 = (const float*)d_in[0];
    const float* feat1 = (const float*)d_in[1];
    const float* feat2 = (const float*)d_in[2];
    const float* boxes = (const float*)d_in[3];
    const int*   img_h = (const int*)d_in[4];
    const int*   img_w = (const int*)d_in[5];
    float* out = (float*)d_out;

    int N = in_sizes[3] / 4;

    prep0_kernel<<<dim3(10, 200, 4), 256>>>(feat0);
    prep1_kernel<<<dim3(5, 100, 4), 256>>>(feat1);
    prep2_kernel<<<dim3(3, 100, 4), 256>>>(feat2);
    roi_kernel<<<dim3(N, 7), 96>>>(boxes, img_h, img_w, out);
}

// round 6
// speedup vs baseline: 1.8175x; 1.0444x over previous
#include <cuda_runtime.h>
#include <cuda_fp16.h>
#include <cstdint>

#define H0 200
#define W0 304
#define H1 100
#define W1 152
#define H2 50
#define W2 76
#define HW0 (H0*W0)
#define C_TOT 768

// Fused HWC fp16 map, 16B-aligned: [H0*W0][768ch]
__device__ uint4 g_fused[(size_t)HW0 * (C_TOT/8)];

// ---------------------------------------------------------------------------
// prep0: transpose feat0 (CHW fp32) -> g_fused channels [0,256) (HWC fp16)
// ---------------------------------------------------------------------------
__global__ __launch_bounds__(256) void prep0_kernel(const float* __restrict__ f0) {
    __shared__ float tile[64][33];
    int y = blockIdx.y, xblk = blockIdx.x * 32, g = blockIdx.z;
    int warp = threadIdx.x >> 5, lane = threadIdx.x & 31;
    int x = xblk + lane;
    int c0 = g * 64;
    if (x < W0) {
        const float* src = f0 + (size_t)c0 * HW0 + y * W0 + x;
#pragma unroll
        for (int p = 0; p < 8; p++) {
            int cl = warp * 8 + p;
            tile[cl][lane] = __ldg(src + (size_t)cl * HW0);
        }
    }
    __syncthreads();
    __half* gf = (__half*)g_fused;
#pragma unroll
    for (int q = 0; q < 4; q++) {
        int px = warp * 4 + q, xg = xblk + px;
        if (xg < W0) {
            __half2 v = __floats2half2_rn(tile[2 * lane][px], tile[2 * lane + 1][px]);
            *(__half2*)(gf + (size_t)(y * W0 + xg) * C_TOT + c0 + 2 * lane) = v;
        }
    }
}

// ---------------------------------------------------------------------------
// prep1: 2x upsample feat1 -> channels [256,512). Constant-phase separable.
// ---------------------------------------------------------------------------
#define P1_PAD 65
__global__ __launch_bounds__(256) void prep1_kernel(const float* __restrict__ f1) {
    __shared__ __half tile[2 * 64 * P1_PAD];
    int Y  = blockIdx.y;
    int xb = blockIdx.x * 64;
    int cb = blockIdx.z * 64;
    int warp = threadIdx.x >> 5, lane = threadIdx.x & 31;
    int j  = xb / 2 + lane;
    int xm = max(j - 1, 0), xc = min(j, W1 - 1), xp = min(j + 1, W1 - 1);
    int r0 = max(Y - 1, 0), r1 = Y, r2 = min(Y + 1, H1 - 1);
#pragma unroll
    for (int p = 0; p < 8; p++) {
        int cl = warp * 8 + p;
        const float* pl = f1 + (size_t)(cb + cl) * (H1 * W1);
        float v00 = __ldg(pl + r0 * W1 + xm), v01 = __ldg(pl + r0 * W1 + xc), v02 = __ldg(pl + r0 * W1 + xp);
        float v10 = __ldg(pl + r1 * W1 + xm), v11 = __ldg(pl + r1 * W1 + xc), v12 = __ldg(pl + r1 * W1 + xp);
        float v20 = __ldg(pl + r2 * W1 + xm), v21 = __ldg(pl + r2 * W1 + xc), v22 = __ldg(pl + r2 * W1 + xp);
        float a0 = 0.25f * v00 + 0.75f * v01, b0 = 0.75f * v01 + 0.25f * v02;
        float a1 = 0.25f * v10 + 0.75f * v11, b1 = 0.75f * v11 + 0.25f * v12;
        float a2 = 0.25f * v20 + 0.75f * v21, b2 = 0.75f * v21 + 0.25f * v22;
        float e0 = 0.25f * a0 + 0.75f * a1, o0 = 0.25f * b0 + 0.75f * b1;
        float e1 = 0.75f * a1 + 0.25f * a2, o1 = 0.75f * b1 + 0.25f * b2;
        int px = 2 * lane;
        tile[(0 * 64 + px)     * P1_PAD + cl] = __float2half_rn(e0);
        tile[(0 * 64 + px + 1) * P1_PAD + cl] = __float2half_rn(o0);
        tile[(1 * 64 + px)     * P1_PAD + cl] = __float2half_rn(e1);
        tile[(1 * 64 + px + 1) * P1_PAD + cl] = __float2half_rn(o1);
    }
    __syncthreads();
    __half* gf = (__half*)g_fused;
    for (int i = warp; i < 128; i += 8) {
        int row = i >> 6, px = i & 63;
        int xg = xb + px;
        if (xg < W0) {
            __half lo = tile[(row * 64 + px) * P1_PAD + 2 * lane];
            __half hi = tile[(row * 64 + px) * P1_PAD + 2 * lane + 1];
            *(__half2*)(gf + (size_t)((2 * Y + row) * W0 + xg) * C_TOT + 256 + cb + 2 * lane)
                = __halves2half2(lo, hi);
        }
    }
}

// ---------------------------------------------------------------------------
// prep2: 4x upsample feat2 -> channels [512,768). Constant-phase separable.
// ---------------------------------------------------------------------------
#define P2_PAD 65
__global__ __launch_bounds__(256) void prep2_kernel(const float* __restrict__ f2) {
    __shared__ __half tile[2 * 128 * P2_PAD];
    int yb = blockIdx.y;
    int Y = yb >> 1, half = yb & 1;
    int xb = blockIdx.x * 128;
    int cb = blockIdx.z * 64;
    int warp = threadIdx.x >> 5, lane = threadIdx.x & 31;
    int j  = xb / 4 + lane;
    int xm = max(j - 1, 0), xc = min(j, W2 - 1), xp = min(j + 1, W2 - 1);
    int ra = half ? Y : max(Y - 1, 0);
    int rb = half ? min(Y + 1, H2 - 1) : Y;
    float wya0, wyb0, wya1, wyb1;
    if (half == 0) { wya0 = 0.375f; wyb0 = 0.625f; wya1 = 0.125f; wyb1 = 0.875f; }
    else           { wya0 = 0.875f; wyb0 = 0.125f; wya1 = 0.625f; wyb1 = 0.375f; }
#pragma unroll
    for (int p = 0; p < 8; p++) {
        int cl = warp * 8 + p;
        const float* pl = f2 + (size_t)(cb + cl) * (H2 * W2);
        float va0 = __ldg(pl + ra * W2 + xm), va1 = __ldg(pl + ra * W2 + xc), va2 = __ldg(pl + ra * W2 + xp);
        float vb0 = __ldg(pl + rb * W2 + xm), vb1 = __ldg(pl + rb * W2 + xc), vb2 = __ldg(pl + rb * W2 + xp);
        float qa[4], qb[4];
        qa[0] = 0.375f * va0 + 0.625f * va1; qa[1] = 0.125f * va0 + 0.875f * va1;
        qa[2] = 0.875f * va1 + 0.125f * va2; qa[3] = 0.625f * va1 + 0.375f * va2;
        qb[0] = 0.375f * vb0 + 0.625f * vb1; qb[1] = 0.125f * vb0 + 0.875f * vb1;
        qb[2] = 0.875f * vb1 + 0.125f * vb2; qb[3] = 0.625f * vb1 + 0.375f * vb2;
        int px = 4 * lane;
#pragma unroll
        for (int q = 0; q < 4; q++) {
            float o0 = wya0 * qa[q] + wyb0 * qb[q];
            float o1 = wya1 * qa[q] + wyb1 * qb[q];
            tile[(0 * 128 + px + q) * P2_PAD + cl] = __float2half_rn(o0);
            tile[(1 * 128 + px + q) * P2_PAD + cl] = __float2half_rn(o1);
        }
    }
    __syncthreads();
    __half* gf = (__half*)g_fused;
    int ybase = 4 * Y + 2 * half;
    for (int i = warp; i < 256; i += 8) {
        int row = i >> 7, px = i & 127;
        int xg = xb + px;
        if (xg < W0) {
            __half lo = tile[(row * 128 + px) * P2_PAD + 2 * lane];
            __half hi = tile[(row * 128 + px) * P2_PAD + 2 * lane + 1];
            *(__half2*)(gf + (size_t)((ybase + row) * W0 + xg) * C_TOT + 512 + cb + 2 * lane)
                = __halves2half2(lo, hi);
        }
    }
}

// ---------------------------------------------------------------------------
// RoIAlign: grid (N, 2 slabs of 384ch, 7 oh), block 96.
// tid = uint2 channel index (4 ch) within slab; warp load = 256B coalesced.
// Static fully-unrolled 7 x 16 tap loop; smem-staged coalesced stores.
// ---------------------------------------------------------------------------
#define CPU2 (C_TOT/4)   // 192 uint2 per pixel row

__global__ __launch_bounds__(96) void roi_kernel(
    const float* __restrict__ boxes,
    const int*   __restrict__ img_h,
    const int*   __restrict__ img_w,
    float* __restrict__ out)
{
    int roi  = blockIdx.x;
    int slab = blockIdx.y;                  // 0..1 (384 channels each)
    int oh   = blockIdx.z;                  // 0..6
    int tid  = threadIdx.x;                 // 0..95 = uint2 index in slab

    __shared__ int   sxo[14][2];            // x corners (uint2 units)
    __shared__ float swx[14][2];
    __shared__ int   syo[2][2];             // y corners (uint2 units)
    __shared__ float swy[2][2];
    __shared__ float s_out[384][7];

    if (tid < 16) {
        bool isx = tid < 14;
        int  s, bin;
        if (isx) { s = tid;      bin = s >> 1; }
        else     { s = tid - 14; bin = oh;     }
        float offs = 0.25f + 0.5f * (float)(isx ? (s & 1) : s);

        float scale = isx ? ((float)W0 / (float)__ldg(img_w))
                          : ((float)H0 / (float)__ldg(img_h));
        float p1 = __ldg(boxes + roi * 4 + (isx ? 0 : 1)) * scale;
        float p2 = __ldg(boxes + roi * 4 + (isx ? 2 : 3)) * scale;
        float bs = fmaxf(p2 - p1, 1.0f) * (1.0f / 7.0f);
        float P  = p1 + ((float)bin + offs) * bs;

        int lim = isx ? W0 : H0;
        bool valid = (P >= -1.0f) && (P <= (float)lim);
        float Pc = fminf(fmaxf(P, 0.0f), (float)(lim - 1));
        int p0  = (int)Pc;
        int p1i = min(p0 + 1, lim - 1);
        float l  = Pc - (float)p0;
        float w0 = valid ? (1.0f - l) : 0.0f;
        float w1 = valid ? l : 0.0f;

        if (isx) {
            sxo[s][0] = p0 * CPU2;   sxo[s][1] = p1i * CPU2;
            swx[s][0] = w0;          swx[s][1] = w1;
        } else {
            syo[s][0] = p0 * (W0 * CPU2);   syo[s][1] = p1i * (W0 * CPU2);
            swy[s][0] = w0;                 swy[s][1] = w1;
        }
    }
    __syncthreads();

    const uint2* fc = (const uint2*)g_fused + slab * 96 + tid;

    int   ya0 = syo[0][0], ya1 = syo[0][1];
    int   yb0 = syo[1][0], yb1 = syo[1][1];
    float wa0 = swy[0][0], wa1 = swy[0][1];
    float wb0 = swy[1][0], wb1 = swy[1][1];

#pragma unroll
    for (int ow = 0; ow < 7; ow++) {
        float a0 = 0, a1 = 0, a2 = 0, a3 = 0;
#pragma unroll
        for (int sx = 0; sx < 2; sx++) {
            int s = 2 * ow + sx;
            int x0 = sxo[s][0], x1 = sxo[s][1];
            float u0 = swx[s][0], u1 = swx[s][1];
#pragma unroll
            for (int t = 0; t < 8; t++) {
                int   yo; float wy; int xo; float ux;
                switch (t & 3) {
                    case 0: yo = ya0; wy = wa0; break;
                    case 1: yo = ya1; wy = wa1; break;
                    case 2: yo = yb0; wy = wb0; break;
                    default: yo = yb1; wy = wb1; break;
                }
                if (t < 4) { xo = x0; ux = u0; } else { xo = x1; ux = u1; }
                float k = wy * ux;
                uint2 v = __ldg(fc + yo + xo);
                float2 f0 = __half22float2(*(const __half2*)&v.x);
                float2 f1 = __half22float2(*(const __half2*)&v.y);
                a0 += k * f0.x; a1 += k * f0.y;
                a2 += k * f1.x; a3 += k * f1.y;
            }
        }
        s_out[4 * tid + 0][ow] = a0 * 0.25f;
        s_out[4 * tid + 1][ow] = a1 * 0.25f;
        s_out[4 * tid + 2][ow] = a2 * 0.25f;
        s_out[4 * tid + 3][ow] = a3 * 0.25f;
    }
    __syncthreads();

    // coalesced-ish store of the block's [384ch x 7ow] chunk
    float* base = out + ((size_t)roi * C_TOT + slab * 384) * 49 + oh * 7;
#pragma unroll 4
    for (int i = tid; i < 384 * 7; i += 96) {
        int c = i / 7, owv = i - 7 * c;
        base[(size_t)c * 49 + owv] = s_out[c][owv];
    }
}

// ---------------------------------------------------------------------------
// Launch
// ---------------------------------------------------------------------------
extern "C" void kernel_launch(void* const* d_in, const int* in_sizes, int n_in,
                              void* d_out, int out_size) {
    const float* feat0 = (const float*)d_in[0];
    const float* feat1 = (const float*)d_in[1];
    const float* feat2 = (const float*)d_in[2];
    const float* boxes = (const float*)d_in[3];
    const int*   img_h = (const int*)d_in[4];
    const int*   img_w = (const int*)d_in[5];
    float* out = (float*)d_out;

    int N = in_sizes[3] / 4;

    prep0_kernel<<<dim3(10, 200, 4), 256>>>(feat0);
    prep1_kernel<<<dim3(5, 100, 4), 256>>>(feat1);
    prep2_kernel<<<dim3(3, 100, 4), 256>>>(feat2);
    roi_kernel<<<dim3(N, 2, 7), 96>>>(boxes, img_h, img_w, out);
}

// round 7
// speedup vs baseline: 1.8210x; 1.0019x over previous
#include <cuda_runtime.h>
#include <cuda_fp16.h>
#include <cstdint>

#define H0 200
#define W0 304
#define H1 100
#define W1 152
#define H2 50
#define W2 76
#define HW0 (H0*W0)
#define C_TOT 768

// Fused HWC fp16 map, 16B-aligned: [H0*W0][768ch]
__device__ uint4 g_fused[(size_t)HW0 * (C_TOT/8)];

// ---------------------------------------------------------------------------
// prep0: transpose feat0 (CHW fp32) -> g_fused channels [0,256) (HWC fp16)
// ---------------------------------------------------------------------------
__global__ __launch_bounds__(256) void prep0_kernel(const float* __restrict__ f0) {
    __shared__ float tile[64][33];
    int y = blockIdx.y, xblk = blockIdx.x * 32, g = blockIdx.z;
    int warp = threadIdx.x >> 5, lane = threadIdx.x & 31;
    int x = xblk + lane;
    int c0 = g * 64;
    if (x < W0) {
        const float* src = f0 + (size_t)c0 * HW0 + y * W0 + x;
#pragma unroll
        for (int p = 0; p < 8; p++) {
            int cl = warp * 8 + p;
            tile[cl][lane] = __ldg(src + (size_t)cl * HW0);
        }
    }
    __syncthreads();
    __half* gf = (__half*)g_fused;
#pragma unroll
    for (int q = 0; q < 4; q++) {
        int px = warp * 4 + q, xg = xblk + px;
        if (xg < W0) {
            __half2 v = __floats2half2_rn(tile[2 * lane][px], tile[2 * lane + 1][px]);
            *(__half2*)(gf + (size_t)(y * W0 + xg) * C_TOT + c0 + 2 * lane) = v;
        }
    }
}

// ---------------------------------------------------------------------------
// prep1: 2x upsample feat1 -> channels [256,512). Constant-phase separable.
// ---------------------------------------------------------------------------
#define P1_PAD 65
__global__ __launch_bounds__(256) void prep1_kernel(const float* __restrict__ f1) {
    __shared__ __half tile[2 * 64 * P1_PAD];
    int Y  = blockIdx.y;
    int xb = blockIdx.x * 64;
    int cb = blockIdx.z * 64;
    int warp = threadIdx.x >> 5, lane = threadIdx.x & 31;
    int j  = xb / 2 + lane;
    int xm = max(j - 1, 0), xc = min(j, W1 - 1), xp = min(j + 1, W1 - 1);
    int r0 = max(Y - 1, 0), r1 = Y, r2 = min(Y + 1, H1 - 1);
#pragma unroll
    for (int p = 0; p < 8; p++) {
        int cl = warp * 8 + p;
        const float* pl = f1 + (size_t)(cb + cl) * (H1 * W1);
        float v00 = __ldg(pl + r0 * W1 + xm), v01 = __ldg(pl + r0 * W1 + xc), v02 = __ldg(pl + r0 * W1 + xp);
        float v10 = __ldg(pl + r1 * W1 + xm), v11 = __ldg(pl + r1 * W1 + xc), v12 = __ldg(pl + r1 * W1 + xp);
        float v20 = __ldg(pl + r2 * W1 + xm), v21 = __ldg(pl + r2 * W1 + xc), v22 = __ldg(pl + r2 * W1 + xp);
        float a0 = 0.25f * v00 + 0.75f * v01, b0 = 0.75f * v01 + 0.25f * v02;
        float a1 = 0.25f * v10 + 0.75f * v11, b1 = 0.75f * v11 + 0.25f * v12;
        float a2 = 0.25f * v20 + 0.75f * v21, b2 = 0.75f * v21 + 0.25f * v22;
        float e0 = 0.25f * a0 + 0.75f * a1, o0 = 0.25f * b0 + 0.75f * b1;
        float e1 = 0.75f * a1 + 0.25f * a2, o1 = 0.75f * b1 + 0.25f * b2;
        int px = 2 * lane;
        tile[(0 * 64 + px)     * P1_PAD + cl] = __float2half_rn(e0);
        tile[(0 * 64 + px + 1) * P1_PAD + cl] = __float2half_rn(o0);
        tile[(1 * 64 + px)     * P1_PAD + cl] = __float2half_rn(e1);
        tile[(1 * 64 + px + 1) * P1_PAD + cl] = __float2half_rn(o1);
    }
    __syncthreads();
    __half* gf = (__half*)g_fused;
    for (int i = warp; i < 128; i += 8) {
        int row = i >> 6, px = i & 63;
        int xg = xb + px;
        if (xg < W0) {
            __half lo = tile[(row * 64 + px) * P1_PAD + 2 * lane];
            __half hi = tile[(row * 64 + px) * P1_PAD + 2 * lane + 1];
            *(__half2*)(gf + (size_t)((2 * Y + row) * W0 + xg) * C_TOT + 256 + cb + 2 * lane)
                = __halves2half2(lo, hi);
        }
    }
}

// ---------------------------------------------------------------------------
// prep2: 4x upsample feat2 -> channels [512,768). Constant-phase separable.
// ---------------------------------------------------------------------------
#define P2_PAD 65
__global__ __launch_bounds__(256) void prep2_kernel(const float* __restrict__ f2) {
    __shared__ __half tile[2 * 128 * P2_PAD];
    int yb = blockIdx.y;
    int Y = yb >> 1, half = yb & 1;
    int xb = blockIdx.x * 128;
    int cb = blockIdx.z * 64;
    int warp = threadIdx.x >> 5, lane = threadIdx.x & 31;
    int j  = xb / 4 + lane;
    int xm = max(j - 1, 0), xc = min(j, W2 - 1), xp = min(j + 1, W2 - 1);
    int ra = half ? Y : max(Y - 1, 0);
    int rb = half ? min(Y + 1, H2 - 1) : Y;
    float wya0, wyb0, wya1, wyb1;
    if (half == 0) { wya0 = 0.375f; wyb0 = 0.625f; wya1 = 0.125f; wyb1 = 0.875f; }
    else           { wya0 = 0.875f; wyb0 = 0.125f; wya1 = 0.625f; wyb1 = 0.375f; }
#pragma unroll
    for (int p = 0; p < 8; p++) {
        int cl = warp * 8 + p;
        const float* pl = f2 + (size_t)(cb + cl) * (H2 * W2);
        float va0 = __ldg(pl + ra * W2 + xm), va1 = __ldg(pl + ra * W2 + xc), va2 = __ldg(pl + ra * W2 + xp);
        float vb0 = __ldg(pl + rb * W2 + xm), vb1 = __ldg(pl + rb * W2 + xc), vb2 = __ldg(pl + rb * W2 + xp);
        float qa[4], qb[4];
        qa[0] = 0.375f * va0 + 0.625f * va1; qa[1] = 0.125f * va0 + 0.875f * va1;
        qa[2] = 0.875f * va1 + 0.125f * va2; qa[3] = 0.625f * va1 + 0.375f * va2;
        qb[0] = 0.375f * vb0 + 0.625f * vb1; qb[1] = 0.125f * vb0 + 0.875f * vb1;
        qb[2] = 0.875f * vb1 + 0.125f * vb2; qb[3] = 0.625f * vb1 + 0.375f * vb2;
        int px = 4 * lane;
#pragma unroll
        for (int q = 0; q < 4; q++) {
            float o0 = wya0 * qa[q] + wyb0 * qb[q];
            float o1 = wya1 * qa[q] + wyb1 * qb[q];
            tile[(0 * 128 + px + q) * P2_PAD + cl] = __float2half_rn(o0);
            tile[(1 * 128 + px + q) * P2_PAD + cl] = __float2half_rn(o1);
        }
    }
    __syncthreads();
    __half* gf = (__half*)g_fused;
    int ybase = 4 * Y + 2 * half;
    for (int i = warp; i < 256; i += 8) {
        int row = i >> 7, px = i & 127;
        int xg = xb + px;
        if (xg < W0) {
            __half lo = tile[(row * 128 + px) * P2_PAD + 2 * lane];
            __half hi = tile[(row * 128 + px) * P2_PAD + 2 * lane + 1];
            *(__half2*)(gf + (size_t)((ybase + row) * W0 + xg) * C_TOT + 512 + cb + 2 * lane)
                = __halves2half2(lo, hi);
        }
    }
}

// ---------------------------------------------------------------------------
// RoIAlign: grid (N, 2 slabs of 384ch, 7 oh), block 96.
// tid = uint2 channel index (4 ch) within slab; warp load = 256B coalesced.
// Static fully-unrolled 7 x 16 tap loop; smem-staged coalesced stores.
// ---------------------------------------------------------------------------
#define CPU2 (C_TOT/4)   // 192 uint2 per pixel row

__global__ __launch_bounds__(96) void roi_kernel(
    const float* __restrict__ boxes,
    const int*   __restrict__ img_h,
    const int*   __restrict__ img_w,
    float* __restrict__ out)
{
    int roi  = blockIdx.x;
    int slab = blockIdx.y;                  // 0..1 (384 channels each)
    int oh   = blockIdx.z;                  // 0..6
    int tid  = threadIdx.x;                 // 0..95 = uint2 index in slab

    __shared__ int   sxo[14][2];            // x corners (uint2 units)
    __shared__ float swx[14][2];
    __shared__ int   syo[2][2];             // y corners (uint2 units)
    __shared__ float swy[2][2];
    __shared__ float s_out[384][7];

    if (tid < 16) {
        bool isx = tid < 14;
        int  s, bin;
        if (isx) { s = tid;      bin = s >> 1; }
        else     { s = tid - 14; bin = oh;     }
        float offs = 0.25f + 0.5f * (float)(isx ? (s & 1) : s);

        float scale = isx ? ((float)W0 / (float)__ldg(img_w))
                          : ((float)H0 / (float)__ldg(img_h));
        float p1 = __ldg(boxes + roi * 4 + (isx ? 0 : 1)) * scale;
        float p2 = __ldg(boxes + roi * 4 + (isx ? 2 : 3)) * scale;
        float bs = fmaxf(p2 - p1, 1.0f) * (1.0f / 7.0f);
        float P  = p1 + ((float)bin + offs) * bs;

        int lim = isx ? W0 : H0;
        bool valid = (P >= -1.0f) && (P <= (float)lim);
        float Pc = fminf(fmaxf(P, 0.0f), (float)(lim - 1));
        int p0  = (int)Pc;
        int p1i = min(p0 + 1, lim - 1);
        float l  = Pc - (float)p0;
        float w0 = valid ? (1.0f - l) : 0.0f;
        float w1 = valid ? l : 0.0f;

        if (isx) {
            sxo[s][0] = p0 * CPU2;   sxo[s][1] = p1i * CPU2;
            swx[s][0] = w0;          swx[s][1] = w1;
        } else {
            syo[s][0] = p0 * (W0 * CPU2);   syo[s][1] = p1i * (W0 * CPU2);
            swy[s][0] = w0;                 swy[s][1] = w1;
        }
    }
    __syncthreads();

    const uint2* fc = (const uint2*)g_fused + slab * 96 + tid;

    int   ya0 = syo[0][0], ya1 = syo[0][1];
    int   yb0 = syo[1][0], yb1 = syo[1][1];
    float wa0 = swy[0][0], wa1 = swy[0][1];
    float wb0 = swy[1][0], wb1 = swy[1][1];

#pragma unroll
    for (int ow = 0; ow < 7; ow++) {
        float a0 = 0, a1 = 0, a2 = 0, a3 = 0;
#pragma unroll
        for (int sx = 0; sx < 2; sx++) {
            int s = 2 * ow + sx;
            int x0 = sxo[s][0], x1 = sxo[s][1];
            float u0 = swx[s][0], u1 = swx[s][1];
#pragma unroll
            for (int t = 0; t < 8; t++) {
                int   yo; float wy; int xo; float ux;
                switch (t & 3) {
                    case 0: yo = ya0; wy = wa0; break;
                    case 1: yo = ya1; wy = wa1; break;
                    case 2: yo = yb0; wy = wb0; break;
                    default: yo = yb1; wy = wb1; break;
                }
                if (t < 4) { xo = x0; ux = u0; } else { xo = x1; ux = u1; }
                float k = wy * ux;
                uint2 v = __ldg(fc + yo + xo);
                float2 f0 = __half22float2(*(const __half2*)&v.x);
                float2 f1 = __half22float2(*(const __half2*)&v.y);
                a0 += k * f0.x; a1 += k * f0.y;
                a2 += k * f1.x; a3 += k * f1.y;
            }
        }
        s_out[4 * tid + 0][ow] = a0 * 0.25f;
        s_out[4 * tid + 1][ow] = a1 * 0.25f;
        s_out[4 * tid + 2][ow] = a2 * 0.25f;
        s_out[4 * tid + 3][ow] = a3 * 0.25f;
    }
    __syncthreads();

    // coalesced-ish store of the block's [384ch x 7ow] chunk
    float* base = out + ((size_t)roi * C_TOT + slab * 384) * 49 + oh * 7;
#pragma unroll 4
    for (int i = tid; i < 384 * 7; i += 96) {
        int c = i / 7, owv = i - 7 * c;
        base[(size_t)c * 49 + owv] = s_out[c][owv];
    }
}

// ---------------------------------------------------------------------------
// Launch
// ---------------------------------------------------------------------------
extern "C" void kernel_launch(void* const* d_in, const int* in_sizes, int n_in,
                              void* d_out, int out_size) {
    const float* feat0 = (const float*)d_in[0];
    const float* feat1 = (const float*)d_in[1];
    const float* feat2 = (const float*)d_in[2];
    const float* boxes = (const float*)d_in[3];
    const int*   img_h = (const int*)d_in[4];
    const int*   img_w = (const int*)d_in[5];
    float* out = (float*)d_out;

    int N = in_sizes[3] / 4;

    prep0_kernel<<<dim3(10, 200, 4), 256>>>(feat0);
    prep1_kernel<<<dim3(5, 100, 4), 256>>>(feat1);
    prep2_kernel<<<dim3(3, 100, 4), 256>>>(feat2);
    roi_kernel<<<dim3(N, 2, 7), 96>>>(boxes, img_h, img_w, out);
}

// round 8
// speedup vs baseline: 2.0366x; 1.1184x over previous
#include <cuda_runtime.h>
#include <cuda_fp16.h>
#include <cstdint>

#define H0 200
#define W0 304
#define H1 100
#define W1 152
#define H2 50
#define W2 76
#define HW0 (H0*W0)
#define C_TOT 768

// Fused HWC fp16 map, 16B-aligned: [H0*W0][96 octets of 8ch]
__device__ uint4 g_fused[(size_t)HW0 * (C_TOT/8)];

// ---------------------------------------------------------------------------
// Unified prep kernel: one launch, three regions run concurrently.
//  region 0 (8000 blocks): transpose feat0 -> ch [0,256)
//  region 1 (2000 blocks): 2x upsample feat1 -> ch [256,512)
//  region 2 (1200 blocks): 4x upsample feat2 -> ch [512,768)
// Interleave 20:5:3 per 28 blocks so all regions are active in every wave.
// ---------------------------------------------------------------------------
#define P1_PAD 65
#define P2_PAD 65
#define PREP_BLOCKS (8000 + 2000 + 1200)

__global__ __launch_bounds__(256) void prep_all(
    const float* __restrict__ f0,
    const float* __restrict__ f1,
    const float* __restrict__ f2)
{
    __shared__ char smem_u[2 * 128 * P2_PAD * 2];   // 33280B union
    int warp = threadIdx.x >> 5, lane = threadIdx.x & 31;
    __half* gf = (__half*)g_fused;

    int gq = blockIdx.x / 28, r = blockIdx.x % 28;
    if (r < 20) {
        // ---------------- region 0: transpose feat0 ----------------
        int idx = gq * 20 + r;
        int xi = idx % 10; int t = idx / 10;
        int y = t % 200;   int g = t / 200;
        int xblk = xi * 32;
        int x = xblk + lane;
        int c0 = g * 64;
        float (*tile)[33] = (float(*)[33])smem_u;
        if (x < W0) {
            const float* src = f0 + (size_t)c0 * HW0 + y * W0 + x;
#pragma unroll
            for (int p = 0; p < 8; p++) {
                int cl = warp * 8 + p;
                tile[cl][lane] = __ldg(src + (size_t)cl * HW0);
            }
        }
        __syncthreads();
#pragma unroll
        for (int q = 0; q < 4; q++) {
            int px = warp * 4 + q, xg = xblk + px;
            if (xg < W0) {
                __half2 v = __floats2half2_rn(tile[2 * lane][px], tile[2 * lane + 1][px]);
                *(__half2*)(gf + (size_t)(y * W0 + xg) * C_TOT + c0 + 2 * lane) = v;
            }
        }
    } else if (r < 25) {
        // ---------------- region 1: 2x upsample feat1 ----------------
        int idx = gq * 5 + (r - 20);
        int xi = idx % 5; int t = idx / 5;
        int Y = t % 100;  int cb = (t / 100) * 64;
        int xb = xi * 64;
        __half* tile = (__half*)smem_u;     // [2*64][P1_PAD]
        int j  = xb / 2 + lane;
        int xm = max(j - 1, 0), xc = min(j, W1 - 1), xp = min(j + 1, W1 - 1);
        int r0 = max(Y - 1, 0), r1 = Y, r2 = min(Y + 1, H1 - 1);
#pragma unroll
        for (int p = 0; p < 8; p++) {
            int cl = warp * 8 + p;
            const float* pl = f1 + (size_t)(cb + cl) * (H1 * W1);
            float v00 = __ldg(pl + r0 * W1 + xm), v01 = __ldg(pl + r0 * W1 + xc), v02 = __ldg(pl + r0 * W1 + xp);
            float v10 = __ldg(pl + r1 * W1 + xm), v11 = __ldg(pl + r1 * W1 + xc), v12 = __ldg(pl + r1 * W1 + xp);
            float v20 = __ldg(pl + r2 * W1 + xm), v21 = __ldg(pl + r2 * W1 + xc), v22 = __ldg(pl + r2 * W1 + xp);
            float a0 = 0.25f * v00 + 0.75f * v01, b0 = 0.75f * v01 + 0.25f * v02;
            float a1 = 0.25f * v10 + 0.75f * v11, b1 = 0.75f * v11 + 0.25f * v12;
            float a2 = 0.25f * v20 + 0.75f * v21, b2 = 0.75f * v21 + 0.25f * v22;
            float e0 = 0.25f * a0 + 0.75f * a1, o0 = 0.25f * b0 + 0.75f * b1;
            float e1 = 0.75f * a1 + 0.25f * a2, o1 = 0.75f * b1 + 0.25f * b2;
            int px = 2 * lane;
            tile[(0 * 64 + px)     * P1_PAD + cl] = __float2half_rn(e0);
            tile[(0 * 64 + px + 1) * P1_PAD + cl] = __float2half_rn(o0);
            tile[(1 * 64 + px)     * P1_PAD + cl] = __float2half_rn(e1);
            tile[(1 * 64 + px + 1) * P1_PAD + cl] = __float2half_rn(o1);
        }
        __syncthreads();
        for (int i = warp; i < 128; i += 8) {
            int row = i >> 6, px = i & 63;
            int xg = xb + px;
            if (xg < W0) {
                __half lo = tile[(row * 64 + px) * P1_PAD + 2 * lane];
                __half hi = tile[(row * 64 + px) * P1_PAD + 2 * lane + 1];
                *(__half2*)(gf + (size_t)((2 * Y + row) * W0 + xg) * C_TOT + 256 + cb + 2 * lane)
                    = __halves2half2(lo, hi);
            }
        }
    } else {
        // ---------------- region 2: 4x upsample feat2 ----------------
        int idx = gq * 3 + (r - 25);
        int xi = idx % 3; int t = idx / 3;
        int yb = t % 100; int cb = (t / 100) * 64;
        int xb = xi * 128;
        __half* tile = (__half*)smem_u;     // [2*128][P2_PAD]
        int Y = yb >> 1, half = yb & 1;
        int j  = xb / 4 + lane;
        int xm = max(j - 1, 0), xc = min(j, W2 - 1), xp = min(j + 1, W2 - 1);
        int ra = half ? Y : max(Y - 1, 0);
        int rb = half ? min(Y + 1, H2 - 1) : Y;
        float wya0, wyb0, wya1, wyb1;
        if (half == 0) { wya0 = 0.375f; wyb0 = 0.625f; wya1 = 0.125f; wyb1 = 0.875f; }
        else           { wya0 = 0.875f; wyb0 = 0.125f; wya1 = 0.625f; wyb1 = 0.375f; }
#pragma unroll
        for (int p = 0; p < 8; p++) {
            int cl = warp * 8 + p;
            const float* pl = f2 + (size_t)(cb + cl) * (H2 * W2);
            float va0 = __ldg(pl + ra * W2 + xm), va1 = __ldg(pl + ra * W2 + xc), va2 = __ldg(pl + ra * W2 + xp);
            float vb0 = __ldg(pl + rb * W2 + xm), vb1 = __ldg(pl + rb * W2 + xc), vb2 = __ldg(pl + rb * W2 + xp);
            float qa[4], qb[4];
            qa[0] = 0.375f * va0 + 0.625f * va1; qa[1] = 0.125f * va0 + 0.875f * va1;
            qa[2] = 0.875f * va1 + 0.125f * va2; qa[3] = 0.625f * va1 + 0.375f * va2;
            qb[0] = 0.375f * vb0 + 0.625f * vb1; qb[1] = 0.125f * vb0 + 0.875f * vb1;
            qb[2] = 0.875f * vb1 + 0.125f * vb2; qb[3] = 0.625f * vb1 + 0.375f * vb2;
            int px = 4 * lane;
#pragma unroll
            for (int q = 0; q < 4; q++) {
                float o0 = wya0 * qa[q] + wyb0 * qb[q];
                float o1 = wya1 * qa[q] + wyb1 * qb[q];
                tile[(0 * 128 + px + q) * P2_PAD + cl] = __float2half_rn(o0);
                tile[(1 * 128 + px + q) * P2_PAD + cl] = __float2half_rn(o1);
            }
        }
        __syncthreads();
        int ybase = 4 * Y + 2 * half;
        for (int i = warp; i < 256; i += 8) {
            int row = i >> 7, px = i & 127;
            int xg = xb + px;
            if (xg < W0) {
                __half lo = tile[(row * 128 + px) * P2_PAD + 2 * lane];
                __half hi = tile[(row * 128 + px) * P2_PAD + 2 * lane + 1];
                *(__half2*)(gf + (size_t)((ybase + row) * W0 + xg) * C_TOT + 512 + cb + 2 * lane)
                    = __halves2half2(lo, hi);
            }
        }
    }
}

// ---------------------------------------------------------------------------
// RoIAlign: grid (N, 7 oh), block 96; thread = one 8-channel octet (uint4).
// Taps accumulated in half2 via HFMA2 (two 8-tap trees + hadd2 combine).
// x/y coordinate tables in smem; 0.25 bin-average folded into y weights.
// Outputs staged packed (STS.128), then semi-coalesced fp32 global store.
// ---------------------------------------------------------------------------
#define OPP 96   // uint4 octets per pixel

#define TAP(xo, ux, yo, wy, A) { \
    uint4 v = __ldg(fp + (yo) + (xo)); \
    __half2 kh = __float2half2_rn((wy) * (ux)); \
    A[0] = __hfma2(kh, *(__half2*)&v.x, A[0]); \
    A[1] = __hfma2(kh, *(__half2*)&v.y, A[1]); \
    A[2] = __hfma2(kh, *(__half2*)&v.z, A[2]); \
    A[3] = __hfma2(kh, *(__half2*)&v.w, A[3]); }

__global__ __launch_bounds__(96, 8) void roi_kernel(
    const float* __restrict__ boxes,
    const int*   __restrict__ img_h,
    const int*   __restrict__ img_w,
    float* __restrict__ out)
{
    int roi = blockIdx.x;
    int oh  = blockIdx.y;
    int tid = threadIdx.x;          // octet index 0..95

    __shared__ int   sxo[14][2];    // x corner offsets (uint4 units)
    __shared__ float swx[14][2];
    __shared__ int   syo[2][2];     // y corner offsets (uint4 units)
    __shared__ float swy[2][2];     // scaled by 0.25
    __shared__ uint4 s_out4[7 * 96];

    if (tid < 16) {
        bool isx = tid < 14;
        int  s, bin;
        if (isx) { s = tid;      bin = s >> 1; }
        else     { s = tid - 14; bin = oh;     }
        float offs = 0.25f + 0.5f * (float)(isx ? (s & 1) : s);

        float scale = isx ? ((float)W0 / (float)__ldg(img_w))
                          : ((float)H0 / (float)__ldg(img_h));
        float p1 = __ldg(boxes + roi * 4 + (isx ? 0 : 1)) * scale;
        float p2 = __ldg(boxes + roi * 4 + (isx ? 2 : 3)) * scale;
        float bs = fmaxf(p2 - p1, 1.0f) * (1.0f / 7.0f);
        float P  = p1 + ((float)bin + offs) * bs;

        int lim = isx ? W0 : H0;
        bool valid = (P >= -1.0f) && (P <= (float)lim);
        float Pc = fminf(fmaxf(P, 0.0f), (float)(lim - 1));
        int p0  = (int)Pc;
        int p1i = min(p0 + 1, lim - 1);
        float l  = Pc - (float)p0;
        float w0 = valid ? (1.0f - l) : 0.0f;
        float w1 = valid ? l : 0.0f;

        if (isx) {
            sxo[s][0] = p0 * OPP;    sxo[s][1] = p1i * OPP;
            swx[s][0] = w0;          swx[s][1] = w1;
        } else {
            syo[s][0] = p0 * (W0 * OPP);   syo[s][1] = p1i * (W0 * OPP);
            swy[s][0] = w0 * 0.25f;        swy[s][1] = w1 * 0.25f;
        }
    }
    __syncthreads();

    const uint4* fp = g_fused + tid;

    int   ya0 = syo[0][0], ya1 = syo[0][1];
    int   yb0 = syo[1][0], yb1 = syo[1][1];
    float wa0 = swy[0][0], wa1 = swy[0][1];
    float wb0 = swy[1][0], wb1 = swy[1][1];

    const __half2 hz = __float2half2_rn(0.0f);

#pragma unroll
    for (int ow = 0; ow < 7; ow++) {
        int s0 = 2 * ow;
        int   x00 = sxo[s0][0],     x01 = sxo[s0][1];
        float u00 = swx[s0][0],     u01 = swx[s0][1];
        int   x10 = sxo[s0 + 1][0], x11 = sxo[s0 + 1][1];
        float u10 = swx[s0 + 1][0], u11 = swx[s0 + 1][1];

        __half2 A[4] = {hz, hz, hz, hz};
        __half2 B[4] = {hz, hz, hz, hz};

        // sub-sample 0 (8 taps) -> A
        TAP(x00, u00, ya0, wa0, A)  TAP(x00, u00, ya1, wa1, A)
        TAP(x00, u00, yb0, wb0, A)  TAP(x00, u00, yb1, wb1, A)
        TAP(x01, u01, ya0, wa0, A)  TAP(x01, u01, ya1, wa1, A)
        TAP(x01, u01, yb0, wb0, A)  TAP(x01, u01, yb1, wb1, A)
        // sub-sample 1 (8 taps) -> B
        TAP(x10, u10, ya0, wa0, B)  TAP(x10, u10, ya1, wa1, B)
        TAP(x10, u10, yb0, wb0, B)  TAP(x10, u10, yb1, wb1, B)
        TAP(x11, u11, ya0, wa0, B)  TAP(x11, u11, ya1, wa1, B)
        TAP(x11, u11, yb0, wb0, B)  TAP(x11, u11, yb1, wb1, B)

        __half2 c0 = __hadd2(A[0], B[0]);
        __half2 c1 = __hadd2(A[1], B[1]);
        __half2 c2 = __hadd2(A[2], B[2]);
        __half2 c3 = __hadd2(A[3], B[3]);
        uint4 st;
        st.x = *(unsigned*)&c0;  st.y = *(unsigned*)&c1;
        st.z = *(unsigned*)&c2;  st.w = *(unsigned*)&c3;
        s_out4[ow * 96 + tid] = st;
    }
    __syncthreads();

    // global store: element (c, ow) lives at s_half[ow*768 + c]
    const __half* sh = (const __half*)s_out4;
    float* base = out + ((size_t)roi * C_TOT) * 49 + oh * 7;
#pragma unroll 8
    for (int i = tid; i < C_TOT * 7; i += 96) {
        int c = i / 7, owv = i - 7 * c;
        base[(size_t)c * 49 + owv] = __half2float(sh[owv * C_TOT + c]);
    }
}

// ---------------------------------------------------------------------------
// Launch
// ---------------------------------------------------------------------------
extern "C" void kernel_launch(void* const* d_in, const int* in_sizes, int n_in,
                              void* d_out, int out_size) {
    const float* feat0 = (const float*)d_in[0];
    const float* feat1 = (const float*)d_in[1];
    const float* feat2 = (const float*)d_in[2];
    const float* boxes = (const float*)d_in[3];
    const int*   img_h = (const int*)d_in[4];
    const int*   img_w = (const int*)d_in[5];
    float* out = (float*)d_out;

    int N = in_sizes[3] / 4;

    prep_all<<<PREP_BLOCKS, 256>>>(feat0, feat1, feat2);
    roi_kernel<<<dim3(N, 7), 96>>>(boxes, img_h, img_w, out);
}